// round 2
// baseline (speedup 1.0000x reference)
#include <cuda_runtime.h>
#include <cstdint>

// ---------------------------------------------------------------------------
// BinaryTreeComposer on sm_103 (plain target — NO tcgen05 available, harness
// compiles via compute_103 PTX). Use mma.sync tf32 + ldmatrix + cp.async.
//   g = [lh|rh] @ [Wl;Wr]  (M=4096, K=4096, N=8192), then gate epilogue.
// ---------------------------------------------------------------------------

#define BATCH 4096
#define DDIM  2048
#define KTOT  4096
#define NTOT  8192

// scratch (static device globals — allocation-free)
__device__ __align__(128) float g_Apack[(size_t)BATCH * KTOT];   // 64 MB
__device__ __align__(128) float g_Wt[(size_t)NTOT * KTOT];       // 128 MB, [N][K]
__device__ __align__(128) float g_G[(size_t)BATCH * NTOT];       // 128 MB

// ---------------------------------------------------------------------------
// helpers
// ---------------------------------------------------------------------------
__device__ __forceinline__ uint32_t smem_u32(const void* p) {
    uint32_t a;
    asm("{ .reg .u64 t; cvta.to.shared.u64 t, %1; cvt.u32.u64 %0, t; }" : "=r"(a) : "l"(p));
    return a;
}
__device__ __forceinline__ float to_tf32(float x) {
    uint32_t r;
    asm("cvt.rna.tf32.f32 %0, %1;" : "=r"(r) : "f"(x));
    return __uint_as_float(r);
}
__device__ __forceinline__ void cp_async16(uint32_t dst, const void* src) {
    asm volatile("cp.async.cg.shared.global [%0], [%1], 16;" :: "r"(dst), "l"(src) : "memory");
}
#define CP_COMMIT() asm volatile("cp.async.commit_group;" ::: "memory")
#define CP_WAIT(n)  asm volatile("cp.async.wait_group %0;" :: "n"(n) : "memory")

#define LDSM4(r0, r1, r2, r3, addr)                                            \
    asm volatile("ldmatrix.sync.aligned.m8n8.x4.shared.b16 {%0,%1,%2,%3}, [%4];" \
                 : "=r"(r0), "=r"(r1), "=r"(r2), "=r"(r3) : "r"(addr))

#define MMA_TF32(d, a, b)                                                      \
    asm volatile("mma.sync.aligned.m16n8k8.row.col.f32.tf32.tf32.f32 "         \
                 "{%0,%1,%2,%3}, {%4,%5,%6,%7}, {%8,%9}, {%0,%1,%2,%3};"       \
                 : "+f"((d)[0]), "+f"((d)[1]), "+f"((d)[2]), "+f"((d)[3])       \
                 : "r"((a)[0]), "r"((a)[1]), "r"((a)[2]), "r"((a)[3]),          \
                   "r"((b)[0]), "r"((b)[1]))

// ---------------------------------------------------------------------------
// prep A: Apack[m][k] = tf32( k<2048 ? lh[m][k] : rh[m][k-2048] )
// ---------------------------------------------------------------------------
__global__ void prep_A(const float* __restrict__ lh, const float* __restrict__ rh) {
    size_t idx = (size_t)blockIdx.x * blockDim.x + threadIdx.x; // float4 index
    size_t m = idx >> 10;            // 1024 float4 per row
    int kq = (int)(idx & 1023);
    const float* src = (kq < 512) ? lh : rh;
    int kk = (kq & 511) << 2;
    float4 v = *reinterpret_cast<const float4*>(src + m * DDIM + kk);
    float4 w;
    w.x = to_tf32(v.x); w.y = to_tf32(v.y); w.z = to_tf32(v.z); w.w = to_tf32(v.w);
    *reinterpret_cast<float4*>(g_Apack + m * KTOT + ((size_t)kq << 2)) = w;
}

// ---------------------------------------------------------------------------
// prep W: Wt[n][k] = tf32( k<2048 ? Wl[k][n] : Wr[k-2048][n] )  (transpose)
// grid (KTOT/32, NTOT/32), 256 threads, 32x32 tiles
// ---------------------------------------------------------------------------
__global__ void prep_W(const float* __restrict__ Wl, const float* __restrict__ Wr) {
    __shared__ float s[32][33];
    int kb = blockIdx.x * 32;
    int nb = blockIdx.y * 32;
    int t = threadIdx.x;
    int tn = t & 31, tk = t >> 5;   // tk 0..7
#pragma unroll
    for (int i = 0; i < 4; ++i) {
        int k = kb + tk + i * 8;
        const float* src = (k < DDIM) ? (Wl + (size_t)k * NTOT)
                                      : (Wr + (size_t)(k - DDIM) * NTOT);
        s[tk + i * 8][tn] = to_tf32(src[nb + tn]);
    }
    __syncthreads();
#pragma unroll
    for (int i = 0; i < 4; ++i) {
        int n = nb + tk + i * 8;
        g_Wt[(size_t)n * KTOT + kb + tn] = s[tn][tk + i * 8];
    }
}

// ---------------------------------------------------------------------------
// GEMM: g_G = Apack @ Wt^T    (C[m][n] = sum_k A[m][k] * Wt[n][k])
// CTA 256x128, BK=32, 256 thr, 8 warps in 4(m) x 2(n), warp tile 64x64.
// 3-stage cp.async pipeline; XOR-swizzled smem; ldmatrix fragments.
// ---------------------------------------------------------------------------
#define BM 256
#define BN 128
#define BK 32
#define STG 3
#define KSTEPS (KTOT / BK)                 // 128
#define A_BYTES (BM * BK * 4)              // 32768
#define B_BYTES (BN * BK * 4)              // 16384
#define STAGE_BYTES (A_BYTES + B_BYTES)    // 49152
#define SMEM_BYTES (STG * STAGE_BYTES)     // 147456

__device__ __forceinline__ void load_stage(uint32_t sbase, int buf, int ks, int tid,
                                           const float* Ag, const float* Bg) {
    uint32_t as = sbase + buf * STAGE_BYTES;
    uint32_t bs = as + A_BYTES;
    const float* ag = Ag + ks * BK;
#pragma unroll
    for (int i = 0; i < 8; ++i) {
        int id = tid + (i << 8);
        int row = id >> 3, c = id & 7;
        uint32_t dst = as + row * 128 + ((c ^ (row & 7)) << 4);
        cp_async16(dst, ag + (size_t)row * KTOT + (c << 2));
    }
    const float* bg = Bg + ks * BK;
#pragma unroll
    for (int i = 0; i < 4; ++i) {
        int id = tid + (i << 8);
        int row = id >> 3, c = id & 7;
        uint32_t dst = bs + row * 128 + ((c ^ (row & 7)) << 4);
        cp_async16(dst, bg + (size_t)row * KTOT + (c << 2));
    }
}

__device__ __forceinline__ void compute_step(uint32_t aWarp, uint32_t bWarp,
                                             uint32_t aco, uint32_t bco, uint32_t rr,
                                             float (&ac)[4][8][4]) {
#pragma unroll
    for (int kq = 0; kq < 4; ++kq) {
        uint32_t a[4][4];
        uint32_t axor = ((2 * kq + aco) ^ rr) << 4;
#pragma unroll
        for (int mi = 0; mi < 4; ++mi)
            LDSM4(a[mi][0], a[mi][1], a[mi][2], a[mi][3], aWarp + mi * 2048 + axor);
        uint32_t b[8][2];
        uint32_t bxor = ((2 * kq + bco) ^ rr) << 4;
#pragma unroll
        for (int pi = 0; pi < 4; ++pi) {
            uint32_t r0, r1, r2, r3;
            LDSM4(r0, r1, r2, r3, bWarp + pi * 2048 + bxor);
            b[2 * pi][0] = r0; b[2 * pi][1] = r1;
            b[2 * pi + 1][0] = r2; b[2 * pi + 1][1] = r3;
        }
#pragma unroll
        for (int mi = 0; mi < 4; ++mi)
#pragma unroll
            for (int ni = 0; ni < 8; ++ni)
                MMA_TF32(ac[mi][ni], a[mi], b[ni]);
    }
}

__global__ void __launch_bounds__(256, 1) gemm_kernel() {
    extern __shared__ float smem[];
    uint32_t sbase = smem_u32(smem);
    const int tid = threadIdx.x;
    const int lane = tid & 31;
    const int wid = tid >> 5;
    const int wm = wid & 3;      // 0..3 (64-row m slices)
    const int wn = wid >> 2;     // 0..1 (64-col n slices)

    const float* Ag = g_Apack + (size_t)(blockIdx.y * BM) * KTOT;
    const float* Bg = g_Wt + (size_t)(blockIdx.x * BN) * KTOT;

    // per-lane fragment address components
    const uint32_t j = lane >> 3, rr = lane & 7;
    const uint32_t a_row_off = ((j & 1) << 3) + rr;  const uint32_t aco = j >> 1;
    const uint32_t b_row_off = ((j >> 1) << 3) + rr; const uint32_t bco = j & 1;

    float ac[4][8][4];
#pragma unroll
    for (int mi = 0; mi < 4; ++mi)
#pragma unroll
        for (int ni = 0; ni < 8; ++ni)
#pragma unroll
            for (int q = 0; q < 4; ++q) ac[mi][ni][q] = 0.0f;

    // prologue: fill STG-1 stages
#pragma unroll
    for (int s = 0; s < STG - 1; ++s) {
        load_stage(sbase, s, s, tid, Ag, Bg);
        CP_COMMIT();
    }

#pragma unroll 1
    for (int ks = 0; ks < KSTEPS; ++ks) {
        CP_WAIT(STG - 2);
        __syncthreads();
        int nxt = ks + STG - 1;
        if (nxt < KSTEPS) load_stage(sbase, nxt % STG, nxt, tid, Ag, Bg);
        CP_COMMIT();
        int buf = ks % STG;
        uint32_t aWarp = sbase + buf * STAGE_BYTES + (wm * 64 + a_row_off) * 128;
        uint32_t bWarp = sbase + buf * STAGE_BYTES + A_BYTES + (wn * 64 + b_row_off) * 128;
        compute_step(aWarp, bWarp, aco, bco, rr, ac);
    }

    // epilogue -> g_G
    const size_t m0 = (size_t)blockIdx.y * BM + wm * 64;
    const int n0 = blockIdx.x * BN + wn * 64;
    const int gq = lane >> 2, t4 = lane & 3;
#pragma unroll
    for (int mi = 0; mi < 4; ++mi)
#pragma unroll
        for (int ni = 0; ni < 8; ++ni) {
            float* p = g_G + (m0 + mi * 16 + gq) * NTOT + n0 + ni * 8 + 2 * t4;
            float2 v01 = make_float2(ac[mi][ni][0], ac[mi][ni][1]);
            float2 v23 = make_float2(ac[mi][ni][2], ac[mi][ni][3]);
            *reinterpret_cast<float2*>(p) = v01;
            *reinterpret_cast<float2*>(p + (size_t)8 * NTOT) = v23;
        }
}

// ---------------------------------------------------------------------------
// gates: c = sig(i)*tanh(u) + sig(lf)*lc + sig(rf)*rc ; h = tanh(c)
// ---------------------------------------------------------------------------
__device__ __forceinline__ float sigm(float x) { return 1.0f / (1.0f + expf(-x)); }

__global__ void gates_kernel(const float* __restrict__ lc, const float* __restrict__ rc,
                             const float* __restrict__ bl, const float* __restrict__ br,
                             float* __restrict__ out) {
    size_t idx = (size_t)blockIdx.x * blockDim.x + threadIdx.x; // f4 over [4096][512]
    size_t m = idx >> 9;
    int nq = (int)(idx & 511);

    const float4* grow = reinterpret_cast<const float4*>(g_G + m * NTOT);
    float4 gi = grow[nq];
    float4 gl = grow[nq + 512];
    float4 gr = grow[nq + 1024];
    float4 gu = grow[nq + 1536];

    const float4* bl4 = reinterpret_cast<const float4*>(bl);
    const float4* br4 = reinterpret_cast<const float4*>(br);
    float4 bi = bl4[nq];        float4 bi2 = br4[nq];
    float4 bf = bl4[nq + 512];  float4 bf2 = br4[nq + 512];
    float4 bg = bl4[nq + 1024]; float4 bg2 = br4[nq + 1024];
    float4 bu = bl4[nq + 1536]; float4 bu2 = br4[nq + 1536];

    float4 vlc = reinterpret_cast<const float4*>(lc + m * DDIM)[nq];
    float4 vrc = reinterpret_cast<const float4*>(rc + m * DDIM)[nq];

    float4 c, h;
#define GATE1(X)                                                               \
    do {                                                                       \
        float i_ = sigm(gi.X + bi.X + bi2.X);                                  \
        float lf_ = sigm(gl.X + bf.X + bf2.X);                                 \
        float rf_ = sigm(gr.X + bg.X + bg2.X);                                 \
        float u_ = tanhf(gu.X + bu.X + bu2.X);                                 \
        c.X = i_ * u_ + lf_ * vlc.X + rf_ * vrc.X;                             \
        h.X = tanhf(c.X);                                                      \
    } while (0)
    GATE1(x); GATE1(y); GATE1(z); GATE1(w);
#undef GATE1

    reinterpret_cast<float4*>(out + m * DDIM)[nq] = c;
    reinterpret_cast<float4*>(out + (size_t)BATCH * DDIM + m * DDIM)[nq] = h;
}

// ---------------------------------------------------------------------------
// launch — inputs: lc, lh, rc, rh, Wl, bl, Wr, br (all f32)
// out: c [4096,2048] then h [4096,2048]
// ---------------------------------------------------------------------------
extern "C" void kernel_launch(void* const* d_in, const int* in_sizes, int n_in,
                              void* d_out, int out_size) {
    const float* lc = (const float*)d_in[0];
    const float* lh = (const float*)d_in[1];
    const float* rc = (const float*)d_in[2];
    const float* rh = (const float*)d_in[3];
    const float* Wl = (const float*)d_in[4];
    const float* bl = (const float*)d_in[5];
    const float* Wr = (const float*)d_in[6];
    const float* br = (const float*)d_in[7];
    float* out = (float*)d_out;

    prep_A<<<(BATCH * (KTOT / 4)) / 256, 256>>>(lh, rh);
    prep_W<<<dim3(KTOT / 32, NTOT / 32), 256>>>(Wl, Wr);

    cudaFuncSetAttribute(gemm_kernel, cudaFuncAttributeMaxDynamicSharedMemorySize,
                         SMEM_BYTES);
    gemm_kernel<<<dim3(NTOT / BN, BATCH / BM), 256, SMEM_BYTES>>>();

    gates_kernel<<<(BATCH * (DDIM / 4)) / 256, 256>>>(lc, rc, bl, br, out);
}

// round 3
// speedup vs baseline: 1.1060x; 1.1060x over previous
#include <cuda_runtime.h>
#include <cstdint>

// ---------------------------------------------------------------------------
// BinaryTreeComposer on sm_103 (plain target — no tcgen05). tf32 mma.sync.
//   g = [lh|rh] @ [Wl;Wr]  (M=4096, K=4096, N=8192), then gate epilogue.
// R3: GEMM restructured to 128x128 CTA, 2 CTAs/SM for stall overlap.
// ---------------------------------------------------------------------------

#define BATCH 4096
#define DDIM  2048
#define KTOT  4096
#define NTOT  8192

__device__ __align__(128) float g_Apack[(size_t)BATCH * KTOT];   // 64 MB
__device__ __align__(128) float g_Wt[(size_t)NTOT * KTOT];       // 128 MB, [N][K]
__device__ __align__(128) float g_G[(size_t)BATCH * NTOT];       // 128 MB

// ---------------------------------------------------------------------------
// helpers
// ---------------------------------------------------------------------------
__device__ __forceinline__ uint32_t smem_u32(const void* p) {
    uint32_t a;
    asm("{ .reg .u64 t; cvta.to.shared.u64 t, %1; cvt.u32.u64 %0, t; }" : "=r"(a) : "l"(p));
    return a;
}
__device__ __forceinline__ float to_tf32(float x) {
    uint32_t r;
    asm("cvt.rna.tf32.f32 %0, %1;" : "=r"(r) : "f"(x));
    return __uint_as_float(r);
}
__device__ __forceinline__ void cp_async16(uint32_t dst, const void* src) {
    asm volatile("cp.async.cg.shared.global [%0], [%1], 16;" :: "r"(dst), "l"(src) : "memory");
}
#define CP_COMMIT() asm volatile("cp.async.commit_group;" ::: "memory")
#define CP_WAIT(n)  asm volatile("cp.async.wait_group %0;" :: "n"(n) : "memory")

#define LDSM4(r0, r1, r2, r3, addr)                                            \
    asm volatile("ldmatrix.sync.aligned.m8n8.x4.shared.b16 {%0,%1,%2,%3}, [%4];" \
                 : "=r"(r0), "=r"(r1), "=r"(r2), "=r"(r3) : "r"(addr))

#define MMA_TF32(d, a, b)                                                      \
    asm volatile("mma.sync.aligned.m16n8k8.row.col.f32.tf32.tf32.f32 "         \
                 "{%0,%1,%2,%3}, {%4,%5,%6,%7}, {%8,%9}, {%0,%1,%2,%3};"       \
                 : "+f"((d)[0]), "+f"((d)[1]), "+f"((d)[2]), "+f"((d)[3])       \
                 : "r"((a)[0]), "r"((a)[1]), "r"((a)[2]), "r"((a)[3]),          \
                   "r"((b)[0]), "r"((b)[1]))

// ---------------------------------------------------------------------------
// prep A: Apack[m][k] = tf32( k<2048 ? lh[m][k] : rh[m][k-2048] )
// ---------------------------------------------------------------------------
__global__ void prep_A(const float* __restrict__ lh, const float* __restrict__ rh) {
    size_t idx = (size_t)blockIdx.x * blockDim.x + threadIdx.x;
    size_t m = idx >> 10;
    int kq = (int)(idx & 1023);
    const float* src = (kq < 512) ? lh : rh;
    int kk = (kq & 511) << 2;
    float4 v = *reinterpret_cast<const float4*>(src + m * DDIM + kk);
    float4 w;
    w.x = to_tf32(v.x); w.y = to_tf32(v.y); w.z = to_tf32(v.z); w.w = to_tf32(v.w);
    *reinterpret_cast<float4*>(g_Apack + m * KTOT + ((size_t)kq << 2)) = w;
}

// ---------------------------------------------------------------------------
// prep W: Wt[n][k] = tf32( k<2048 ? Wl[k][n] : Wr[k-2048][n] )  (transpose)
// ---------------------------------------------------------------------------
__global__ void prep_W(const float* __restrict__ Wl, const float* __restrict__ Wr) {
    __shared__ float s[32][33];
    int kb = blockIdx.x * 32;
    int nb = blockIdx.y * 32;
    int t = threadIdx.x;
    int tn = t & 31, tk = t >> 5;
#pragma unroll
    for (int i = 0; i < 4; ++i) {
        int k = kb + tk + i * 8;
        const float* src = (k < DDIM) ? (Wl + (size_t)k * NTOT)
                                      : (Wr + (size_t)(k - DDIM) * NTOT);
        s[tk + i * 8][tn] = to_tf32(src[nb + tn]);
    }
    __syncthreads();
#pragma unroll
    for (int i = 0; i < 4; ++i) {
        int n = nb + tk + i * 8;
        g_Wt[(size_t)n * KTOT + kb + tn] = s[tn][tk + i * 8];
    }
}

// ---------------------------------------------------------------------------
// GEMM: g_G = Apack @ Wt^T
// CTA 128x128, BK=32, 128 thr (4 warps 2x2, warp tile 64x64), 3-stage
// cp.async pipeline, XOR-swizzled smem, 2 CTAs/SM.
// ---------------------------------------------------------------------------
#define BM 128
#define BN 128
#define BK 32
#define STG 3
#define KSTEPS (KTOT / BK)                 // 128
#define A_BYTES (BM * BK * 4)              // 16384
#define B_BYTES (BN * BK * 4)              // 16384
#define STAGE_BYTES (A_BYTES + B_BYTES)    // 32768
#define SMEM_BYTES (STG * STAGE_BYTES)     // 98304

__device__ __forceinline__ void load_stage(uint32_t sbase, int buf, int ks, int tid,
                                           const float* Ag, const float* Bg) {
    uint32_t as = sbase + buf * STAGE_BYTES;
    uint32_t bs = as + A_BYTES;
    const float* ag = Ag + ks * BK;
#pragma unroll
    for (int i = 0; i < 8; ++i) {
        int id = tid + (i << 7);           // 0..1023
        int row = id >> 3, c = id & 7;
        uint32_t dst = as + row * 128 + ((c ^ (row & 7)) << 4);
        cp_async16(dst, ag + (size_t)row * KTOT + (c << 2));
    }
    const float* bg = Bg + ks * BK;
#pragma unroll
    for (int i = 0; i < 8; ++i) {
        int id = tid + (i << 7);
        int row = id >> 3, c = id & 7;
        uint32_t dst = bs + row * 128 + ((c ^ (row & 7)) << 4);
        cp_async16(dst, bg + (size_t)row * KTOT + (c << 2));
    }
}

__device__ __forceinline__ void compute_step(uint32_t aWarp, uint32_t bWarp,
                                             uint32_t aco, uint32_t bco, uint32_t rr,
                                             float (&ac)[4][8][4]) {
#pragma unroll
    for (int kq = 0; kq < 4; ++kq) {
        uint32_t a[4][4];
        uint32_t axor = ((2 * kq + aco) ^ rr) << 4;
#pragma unroll
        for (int mi = 0; mi < 4; ++mi)
            LDSM4(a[mi][0], a[mi][1], a[mi][2], a[mi][3], aWarp + mi * 2048 + axor);
        uint32_t b[8][2];
        uint32_t bxor = ((2 * kq + bco) ^ rr) << 4;
#pragma unroll
        for (int pi = 0; pi < 4; ++pi) {
            uint32_t r0, r1, r2, r3;
            LDSM4(r0, r1, r2, r3, bWarp + pi * 2048 + bxor);
            b[2 * pi][0] = r0; b[2 * pi][1] = r1;
            b[2 * pi + 1][0] = r2; b[2 * pi + 1][1] = r3;
        }
#pragma unroll
        for (int mi = 0; mi < 4; ++mi)
#pragma unroll
            for (int ni = 0; ni < 8; ++ni)
                MMA_TF32(ac[mi][ni], a[mi], b[ni]);
    }
}

__global__ void __launch_bounds__(128, 2) gemm_kernel() {
    extern __shared__ float smem[];
    uint32_t sbase = smem_u32(smem);
    const int tid = threadIdx.x;
    const int lane = tid & 31;
    const int wid = tid >> 5;
    const int wm = wid & 1;      // 0..1 (64-row m slices)
    const int wn = wid >> 1;     // 0..1 (64-col n slices)

    const float* Ag = g_Apack + (size_t)(blockIdx.y * BM) * KTOT;
    const float* Bg = g_Wt + (size_t)(blockIdx.x * BN) * KTOT;

    const uint32_t j = lane >> 3, rr = lane & 7;
    const uint32_t a_row_off = ((j & 1) << 3) + rr;  const uint32_t aco = j >> 1;
    const uint32_t b_row_off = ((j >> 1) << 3) + rr; const uint32_t bco = j & 1;

    // precomputed per-stage warp base addresses
    uint32_t aW[STG], bW[STG];
#pragma unroll
    for (int s = 0; s < STG; ++s) {
        aW[s] = sbase + s * STAGE_BYTES + (wm * 64 + a_row_off) * 128;
        bW[s] = sbase + s * STAGE_BYTES + A_BYTES + (wn * 64 + b_row_off) * 128;
    }

    float ac[4][8][4];
#pragma unroll
    for (int mi = 0; mi < 4; ++mi)
#pragma unroll
        for (int ni = 0; ni < 8; ++ni)
#pragma unroll
            for (int q = 0; q < 4; ++q) ac[mi][ni][q] = 0.0f;

#pragma unroll
    for (int s = 0; s < STG - 1; ++s) {
        load_stage(sbase, s, s, tid, Ag, Bg);
        CP_COMMIT();
    }

    int buf = 0;
#pragma unroll 1
    for (int ks = 0; ks < KSTEPS; ++ks) {
        CP_WAIT(1);
        __syncthreads();
        int nxt = ks + STG - 1;
        int nbuf = buf + (STG - 1); if (nbuf >= STG) nbuf -= STG;
        if (nxt < KSTEPS) load_stage(sbase, nbuf, nxt, tid, Ag, Bg);
        CP_COMMIT();
        compute_step(aW[buf], bW[buf], aco, bco, rr, ac);
        if (++buf == STG) buf = 0;
    }

    // epilogue -> g_G
    const size_t m0 = (size_t)blockIdx.y * BM + wm * 64;
    const int n0 = blockIdx.x * BN + wn * 64;
    const int gq = lane >> 2, t4 = lane & 3;
#pragma unroll
    for (int mi = 0; mi < 4; ++mi)
#pragma unroll
        for (int ni = 0; ni < 8; ++ni) {
            float* p = g_G + (m0 + mi * 16 + gq) * NTOT + n0 + ni * 8 + 2 * t4;
            *reinterpret_cast<float2*>(p) = make_float2(ac[mi][ni][0], ac[mi][ni][1]);
            *reinterpret_cast<float2*>(p + (size_t)8 * NTOT) =
                make_float2(ac[mi][ni][2], ac[mi][ni][3]);
        }
}

// ---------------------------------------------------------------------------
// gates: c = sig(i)*tanh(u) + sig(lf)*lc + sig(rf)*rc ; h = tanh(c)
// ---------------------------------------------------------------------------
__device__ __forceinline__ float sigm(float x) { return 1.0f / (1.0f + __expf(-x)); }

__global__ void gates_kernel(const float* __restrict__ lc, const float* __restrict__ rc,
                             const float* __restrict__ bl, const float* __restrict__ br,
                             float* __restrict__ out) {
    size_t idx = (size_t)blockIdx.x * blockDim.x + threadIdx.x;
    size_t m = idx >> 9;
    int nq = (int)(idx & 511);

    const float4* grow = reinterpret_cast<const float4*>(g_G + m * NTOT);
    float4 gi = grow[nq];
    float4 gl = grow[nq + 512];
    float4 gr = grow[nq + 1024];
    float4 gu = grow[nq + 1536];

    const float4* bl4 = reinterpret_cast<const float4*>(bl);
    const float4* br4 = reinterpret_cast<const float4*>(br);
    float4 bi = bl4[nq];        float4 bi2 = br4[nq];
    float4 bf = bl4[nq + 512];  float4 bf2 = br4[nq + 512];
    float4 bg = bl4[nq + 1024]; float4 bg2 = br4[nq + 1024];
    float4 bu = bl4[nq + 1536]; float4 bu2 = br4[nq + 1536];

    float4 vlc = reinterpret_cast<const float4*>(lc + m * DDIM)[nq];
    float4 vrc = reinterpret_cast<const float4*>(rc + m * DDIM)[nq];

    float4 c, h;
#define GATE1(X)                                                               \
    do {                                                                       \
        float i_ = sigm(gi.X + bi.X + bi2.X);                                  \
        float lf_ = sigm(gl.X + bf.X + bf2.X);                                 \
        float rf_ = sigm(gr.X + bg.X + bg2.X);                                 \
        float u_ = tanhf(gu.X + bu.X + bu2.X);                                 \
        c.X = i_ * u_ + lf_ * vlc.X + rf_ * vrc.X;                             \
        h.X = tanhf(c.X);                                                      \
    } while (0)
    GATE1(x); GATE1(y); GATE1(z); GATE1(w);
#undef GATE1

    reinterpret_cast<float4*>(out + m * DDIM)[nq] = c;
    reinterpret_cast<float4*>(out + (size_t)BATCH * DDIM + m * DDIM)[nq] = h;
}

// ---------------------------------------------------------------------------
// launch — inputs: lc, lh, rc, rh, Wl, bl, Wr, br (all f32)
// ---------------------------------------------------------------------------
extern "C" void kernel_launch(void* const* d_in, const int* in_sizes, int n_in,
                              void* d_out, int out_size) {
    const float* lc = (const float*)d_in[0];
    const float* lh = (const float*)d_in[1];
    const float* rc = (const float*)d_in[2];
    const float* rh = (const float*)d_in[3];
    const float* Wl = (const float*)d_in[4];
    const float* bl = (const float*)d_in[5];
    const float* Wr = (const float*)d_in[6];
    const float* br = (const float*)d_in[7];
    float* out = (float*)d_out;

    prep_A<<<(BATCH * (KTOT / 4)) / 256, 256>>>(lh, rh);
    prep_W<<<dim3(KTOT / 32, NTOT / 32), 256>>>(Wl, Wr);

    cudaFuncSetAttribute(gemm_kernel, cudaFuncAttributeMaxDynamicSharedMemorySize,
                         SMEM_BYTES);
    gemm_kernel<<<dim3(NTOT / BN, BATCH / BM), 128, SMEM_BYTES>>>();

    gates_kernel<<<(BATCH * (DDIM / 4)) / 256, 256>>>(lc, rc, bl, br, out);
}